// round 8
// baseline (speedup 1.0000x reference)
#include <cuda_runtime.h>

// CapsuleLayer fused kernel, round 8: round-7 core + NGRP n-group batching for
// L1 weight reuse + merged prep kernel.
// x:      (4, 256, 14, 14) fp32          d_in[0]
// weight: (32, 288, 8, 16) fp32          d_in[1]   [o][k][i][c], k = kk*32+inc
// out:    (4, 512, 12, 12) fp32          d_out     channel = o*16 + c

#define G 4
#define NGRP 4
#define NTHREADS 288
#define NWARPS 9

// Repacked weights: Wt[o][kk][i][c4][lane][4] : 32*9*8*4*32*4 floats
__device__ float g_Wt[32 * 9 * 8 * 4 * 32 * 4];
// Repacked x tiles: T[n][kk][lane=inc][i] : 576*9*32*8 floats = 5.3MB
__device__ float g_tiles[576 * 9 * 32 * 8];

// Merged prep: blocks [0,1152) repack weights, [1152,2448) build x tiles.
__global__ void prep_kernel(const float* __restrict__ W,
                            const float* __restrict__ x)
{
    const int bx = blockIdx.x;
    if (bx < 1152) {
        const int idx = bx * 256 + threadIdx.x;   // 0 .. 294911 float4s
        const int c4 = idx & 3;
        const int i  = (idx >> 2) & 7;
        const int t  = idx >> 5;
        const int k  = t % 288;
        const int o  = t / 288;
        const int kk = k >> 5;
        const int ln = k & 31;
        const int dst4 = (((o * 9 + kk) * 8 + i) * 4 + c4) * 32 + ln;
        reinterpret_cast<float4*>(g_Wt)[dst4] =
            reinterpret_cast<const float4*>(W)[idx];
    } else {
        const int idx = (bx - 1152) * 256 + threadIdx.x;  // 0 .. 331775 float4s
        const int ihalf = idx & 1;
        const int lane  = (idx >> 1) & 31;
        const int t     = idx >> 6;        // n*9 + kk, 0..5183
        const int kk    = t % 9;
        const int n     = t / 9;
        const int b     = n / 144;
        const int rr    = n - b * 144;
        const int oh    = rr / 12;
        const int ow    = rr - oh * 12;
        const int kh    = kk / 3;
        const int kw    = kk - kh * 3;

        const float* src = x + (size_t)b * (256 * 196)
                             + (size_t)(lane * 8 + ihalf * 4) * 196
                             + (oh + kh) * 14 + (ow + kw);
        float4 v;
        v.x = __ldg(src);
        v.y = __ldg(src + 196);
        v.z = __ldg(src + 392);
        v.w = __ldg(src + 588);
        reinterpret_cast<float4*>(g_tiles)[idx] = v;
    }
}

// Reduce 16 values across the full warp with log-halving compaction.
// Output: lane l returns total sum for c = (l & 15).
__device__ __forceinline__ float reduce_warp16(float red[16], int lane)
{
    #pragma unroll
    for (int j = 0; j < 16; j++)
        red[j] += __shfl_xor_sync(0xffffffffu, red[j], 16);
    {
        const bool sel = (lane & 8) != 0;
        #pragma unroll
        for (int j = 0; j < 8; j++) {
            float mine  = sel ? red[j + 8] : red[j];
            float other = sel ? red[j]     : red[j + 8];
            other = __shfl_xor_sync(0xffffffffu, other, 8);
            red[j] = mine + other;
        }
    }
    {
        const bool sel = (lane & 4) != 0;
        #pragma unroll
        for (int j = 0; j < 4; j++) {
            float mine  = sel ? red[j + 4] : red[j];
            float other = sel ? red[j]     : red[j + 4];
            other = __shfl_xor_sync(0xffffffffu, other, 4);
            red[j] = mine + other;
        }
    }
    {
        const bool sel = (lane & 2) != 0;
        #pragma unroll
        for (int j = 0; j < 2; j++) {
            float mine  = sel ? red[j + 2] : red[j];
            float other = sel ? red[j]     : red[j + 2];
            other = __shfl_xor_sync(0xffffffffu, other, 2);
            red[j] = mine + other;
        }
    }
    {
        const bool sel = (lane & 1) != 0;
        float mine  = sel ? red[1] : red[0];
        float other = sel ? red[0] : red[1];
        other = __shfl_xor_sync(0xffffffffu, other, 1);
        red[0] = mine + other;
    }
    return red[0];
}

__global__ __launch_bounds__(NTHREADS, 2)
void caps_kernel(float* __restrict__ out)
{
    __shared__ float s_wsum[NWARPS][G];       // per-warp exp-sum partials
    __shared__ float s_wpart[NWARPS][G * 16]; // per-warp output partials
    __shared__ float s_vout[G * 16];          // squashed output vectors [g][c]

    const int tid  = threadIdx.x;
    const int lane = tid & 31;
    const int warp = tid >> 5;

    const int o = blockIdx.y;
    // Weight base is invariant over the NGRP n-groups -> L1 reuse.
    const float* Wtb = g_Wt + ((size_t)(o * 9 + warp) * 4096) + lane * 4;

    #pragma unroll 1
    for (int j = 0; j < NGRP; j++) {
        const int n0  = (blockIdx.x * NGRP + j) * G;
        const int b   = n0 / 144;
        const int rr  = n0 - b * 144;
        const int oh  = rr / 12;
        const int ow0 = rr - oh * 12;

        const float* Tb0 = g_tiles + (((size_t)n0 * 9 + warp) * 32 + lane) * 8;

        // ---- Priors GEMM: pr[g][c] = sum_i t[g][i] * W[o,k,i,c] ----
        float pr[G][16];
        #pragma unroll
        for (int g = 0; g < G; g++)
            #pragma unroll
            for (int c = 0; c < 16; c++)
                pr[g][c] = 0.0f;

        #pragma unroll
        for (int ii = 0; ii < 8; ii += 4) {
            float t0[G], t1[G], t2[G], t3[G];
            #pragma unroll
            for (int g = 0; g < G; g++) {
                const float4 v = __ldg(reinterpret_cast<const float4*>(
                    Tb0 + (size_t)g * (9 * 32 * 8) + ii));
                t0[g] = v.x; t1[g] = v.y; t2[g] = v.z; t3[g] = v.w;
            }

            #define PROC_I(IOFF, T)                                               \
            {                                                                     \
                _Pragma("unroll")                                                 \
                for (int c4 = 0; c4 < 4; c4++) {                                  \
                    const float4 w = *reinterpret_cast<const float4*>(            \
                        Wtb + ((ii + (IOFF)) * 4 + c4) * 128);                    \
                    _Pragma("unroll")                                             \
                    for (int g = 0; g < G; g++) {                                 \
                        pr[g][c4 * 4 + 0] = fmaf(w.x, T[g], pr[g][c4 * 4 + 0]);   \
                        pr[g][c4 * 4 + 1] = fmaf(w.y, T[g], pr[g][c4 * 4 + 1]);   \
                        pr[g][c4 * 4 + 2] = fmaf(w.z, T[g], pr[g][c4 * 4 + 2]);   \
                        pr[g][c4 * 4 + 3] = fmaf(w.w, T[g], pr[g][c4 * 4 + 3]);   \
                    }                                                             \
                }                                                                 \
            }
            PROC_I(0, t0)
            PROC_I(1, t1)
            PROC_I(2, t2)
            PROC_I(3, t3)
            #undef PROC_I
        }

        // ---- Dynamic routing: fully unrolled 3 iterations ----
        float logit[G];
        #pragma unroll
        for (int g = 0; g < G; g++) logit[g] = 0.0f;

        #pragma unroll
        for (int it = 0; it < 3; it++) {
            float e[G];
            if (it > 0) {
                // exp + denominator reduce (4 sums, one compacted 9-SHFL butterfly)
                #pragma unroll
                for (int g = 0; g < G; g++) e[g] = __expf(logit[g]);
                float d0 = e[0], d1 = e[1], d2 = e[2], d3 = e[3];
                d0 += __shfl_xor_sync(0xffffffffu, d0, 16);
                d1 += __shfl_xor_sync(0xffffffffu, d1, 16);
                d2 += __shfl_xor_sync(0xffffffffu, d2, 16);
                d3 += __shfl_xor_sync(0xffffffffu, d3, 16);
                {
                    const bool sel = (lane & 8) != 0;
                    float m0 = sel ? d2 : d0, o0 = sel ? d0 : d2;
                    float m1 = sel ? d3 : d1, o1 = sel ? d1 : d3;
                    o0 = __shfl_xor_sync(0xffffffffu, o0, 8);
                    o1 = __shfl_xor_sync(0xffffffffu, o1, 8);
                    d0 = m0 + o0; d1 = m1 + o1;
                }
                {
                    const bool sel = (lane & 4) != 0;
                    float m = sel ? d1 : d0, ox = sel ? d0 : d1;
                    ox = __shfl_xor_sync(0xffffffffu, ox, 4);
                    d0 = m + ox;
                }
                d0 += __shfl_xor_sync(0xffffffffu, d0, 2);
                d0 += __shfl_xor_sync(0xffffffffu, d0, 1);
                // lane l (l<16, l%4==0) holds D for g = 2*bit3(l) + bit2(l)
                if (lane < 16 && (lane & 3) == 0)
                    s_wsum[warp][((lane >> 3) << 1) | ((lane >> 2) & 1)] = d0;
            }

            // weighted (or raw, iter 0) route-sum reduction per g
            #pragma unroll
            for (int g = 0; g < G; g++) {
                float red[16];
                if (it == 0) {
                    #pragma unroll
                    for (int c = 0; c < 16; c++) red[c] = pr[g][c];
                } else {
                    #pragma unroll
                    for (int c = 0; c < 16; c++) red[c] = e[g] * pr[g][c];
                }
                const float r0 = reduce_warp16(red, lane);
                if (lane < 16) s_wpart[warp][g * 16 + lane] = r0;
            }
            __syncthreads();

            // Parallel finalize: warp g (g<4) handles group g.
            if (warp < G) {
                const int g = warp;
                float val = 0.0f;
                if (lane < 16) {
                    #pragma unroll
                    for (int w = 0; w < NWARPS; w++)
                        val += s_wpart[w][g * 16 + lane];
                }
                if (it == 0) {
                    val *= (1.0f / 288.0f);
                } else {
                    float dsum = 0.0f;
                    #pragma unroll
                    for (int w = 0; w < NWARPS; w++)
                        dsum += s_wsum[w][g];
                    val = __fdividef(val, dsum);
                }
                float sq = val * val;
                sq += __shfl_xor_sync(0xffffffffu, sq, 8);
                sq += __shfl_xor_sync(0xffffffffu, sq, 4);
                sq += __shfl_xor_sync(0xffffffffu, sq, 2);
                sq += __shfl_xor_sync(0xffffffffu, sq, 1);
                const float scale = __fdividef(sqrtf(sq), 1.0f + sq);
                const float ov = val * scale;
                if (lane < 16) {
                    if (it == 2) {
                        out[(size_t)(b * 512 + o * 16 + lane) * 144
                            + oh * 12 + ow0 + g] = ov;
                    } else {
                        s_vout[g * 16 + lane] = ov;
                    }
                }
            }

            // logits += priors . v
            if (it < 2) {
                __syncthreads();
                #pragma unroll
                for (int g = 0; g < G; g++) {
                    float acc = 0.0f;
                    #pragma unroll
                    for (int c = 0; c < 16; c++)
                        acc = fmaf(pr[g][c], s_vout[g * 16 + c], acc);
                    logit[g] += acc;
                }
            }
        }

        // Close smem reuse window before next n-group's routing writes.
        __syncthreads();
    }
}

extern "C" void kernel_launch(void* const* d_in, const int* in_sizes, int n_in,
                              void* d_out, int out_size)
{
    (void)in_sizes; (void)n_in; (void)out_size;
    const float* x = (const float*)d_in[0];
    const float* w = (const float*)d_in[1];
    float* out = (float*)d_out;

    prep_kernel<<<2448, 256>>>(w, x);  // 1152 repack blocks + 1296 tile blocks

    dim3 grid(144 / NGRP, 32);   // 36 x 32, each block does NGRP n-groups
    caps_kernel<<<grid, NTHREADS>>>(out);
}

// round 9
// speedup vs baseline: 1.1070x; 1.1070x over previous
#include <cuda_runtime.h>

// CapsuleLayer fused kernel, round 9: round-7 structure (proven 156us) +
// merged prep kernel + f32x2 packed GEMM accumulators (unpacked once; routing
// is byte-identical to round 7's scalar code).
// x:      (4, 256, 14, 14) fp32          d_in[0]
// weight: (32, 288, 8, 16) fp32          d_in[1]   [o][k][i][c], k = kk*32+inc
// out:    (4, 512, 12, 12) fp32          d_out     channel = o*16 + c

#define G 4
#define NTHREADS 288
#define NWARPS 9

typedef unsigned long long ull;

// Repacked weights: Wt[o][kk][i][c4][lane][4] : 32*9*8*4*32*4 floats
__device__ float g_Wt[32 * 9 * 8 * 4 * 32 * 4];
// Repacked x tiles: T[n][kk][lane=inc][i] : 576*9*32*8 floats = 5.3MB
__device__ float g_tiles[576 * 9 * 32 * 8];

// Merged prep: blocks [0,1152) repack weights, [1152,2448) build x tiles.
__global__ void prep_kernel(const float* __restrict__ W,
                            const float* __restrict__ x)
{
    const int bx = blockIdx.x;
    if (bx < 1152) {
        const int idx = bx * 256 + threadIdx.x;   // 0 .. 294911 float4s
        const int c4 = idx & 3;
        const int i  = (idx >> 2) & 7;
        const int t  = idx >> 5;
        const int k  = t % 288;
        const int o  = t / 288;
        const int kk = k >> 5;
        const int ln = k & 31;
        const int dst4 = (((o * 9 + kk) * 8 + i) * 4 + c4) * 32 + ln;
        reinterpret_cast<float4*>(g_Wt)[dst4] =
            reinterpret_cast<const float4*>(W)[idx];
    } else {
        const int idx = (bx - 1152) * 256 + threadIdx.x;  // 0 .. 331775 float4s
        const int ihalf = idx & 1;
        const int lane  = (idx >> 1) & 31;
        const int t     = idx >> 6;        // n*9 + kk, 0..5183
        const int kk    = t % 9;
        const int n     = t / 9;
        const int b     = n / 144;
        const int rr    = n - b * 144;
        const int oh    = rr / 12;
        const int ow    = rr - oh * 12;
        const int kh    = kk / 3;
        const int kw    = kk - kh * 3;

        const float* src = x + (size_t)b * (256 * 196)
                             + (size_t)(lane * 8 + ihalf * 4) * 196
                             + (oh + kh) * 14 + (ow + kw);
        float4 v;
        v.x = __ldg(src);
        v.y = __ldg(src + 196);
        v.z = __ldg(src + 392);
        v.w = __ldg(src + 588);
        reinterpret_cast<float4*>(g_tiles)[idx] = v;
    }
}

// ---- packed f32x2 helpers ----
__device__ __forceinline__ ull pk2(float a, float b) {
    ull r; asm("mov.b64 %0, {%1, %2};" : "=l"(r) : "f"(a), "f"(b)); return r;
}
__device__ __forceinline__ void upk(ull v, float& a, float& b) {
    asm("mov.b64 {%0, %1}, %2;" : "=f"(a), "=f"(b) : "l"(v));
}
__device__ __forceinline__ ull fma2(ull a, ull b, ull c) {
    ull d; asm("fma.rn.f32x2 %0, %1, %2, %3;" : "=l"(d) : "l"(a), "l"(b), "l"(c));
    return d;
}

// Reduce 16 values across the full warp with log-halving compaction.
// Output: lane l returns total sum for c = (l & 15).
__device__ __forceinline__ float reduce_warp16(float red[16], int lane)
{
    #pragma unroll
    for (int j = 0; j < 16; j++)
        red[j] += __shfl_xor_sync(0xffffffffu, red[j], 16);
    {
        const bool sel = (lane & 8) != 0;
        #pragma unroll
        for (int j = 0; j < 8; j++) {
            float mine  = sel ? red[j + 8] : red[j];
            float other = sel ? red[j]     : red[j + 8];
            other = __shfl_xor_sync(0xffffffffu, other, 8);
            red[j] = mine + other;
        }
    }
    {
        const bool sel = (lane & 4) != 0;
        #pragma unroll
        for (int j = 0; j < 4; j++) {
            float mine  = sel ? red[j + 4] : red[j];
            float other = sel ? red[j]     : red[j + 4];
            other = __shfl_xor_sync(0xffffffffu, other, 4);
            red[j] = mine + other;
        }
    }
    {
        const bool sel = (lane & 2) != 0;
        #pragma unroll
        for (int j = 0; j < 2; j++) {
            float mine  = sel ? red[j + 2] : red[j];
            float other = sel ? red[j]     : red[j + 2];
            other = __shfl_xor_sync(0xffffffffu, other, 2);
            red[j] = mine + other;
        }
    }
    {
        const bool sel = (lane & 1) != 0;
        float mine  = sel ? red[1] : red[0];
        float other = sel ? red[0] : red[1];
        other = __shfl_xor_sync(0xffffffffu, other, 1);
        red[0] = mine + other;
    }
    return red[0];
}

__global__ __launch_bounds__(NTHREADS, 2)
void caps_kernel(float* __restrict__ out)
{
    __shared__ float s_wsum[NWARPS][G];       // per-warp exp-sum partials
    __shared__ float s_wpart[NWARPS][G * 16]; // per-warp output partials
    __shared__ float s_vout[G * 16];          // squashed output vectors [g][c]

    const int tid  = threadIdx.x;
    const int lane = tid & 31;
    const int warp = tid >> 5;

    const int o   = blockIdx.y;
    const int n0  = blockIdx.x * G;
    const int b   = n0 / 144;
    const int rr  = n0 - b * 144;
    const int oh  = rr / 12;
    const int ow0 = rr - oh * 12;

    // float offset = (o*9+warp)*4096 + (i*4+c4)*128 + lane*4
    const float* Wtb = g_Wt + ((size_t)(o * 9 + warp) * 4096) + lane * 4;
    // tile base: ((n*9+warp)*32+lane)*8
    const float* Tb0 = g_tiles + (((size_t)n0 * 9 + warp) * 32 + lane) * 8;

    // ---- Priors GEMM, packed f32x2: pr2[g][c2] = (c=2*c2, c=2*c2+1) ----
    ull pr2[G][8];
    #pragma unroll
    for (int g = 0; g < G; g++)
        #pragma unroll
        for (int c2 = 0; c2 < 8; c2++)
            pr2[g][c2] = 0ull;

    #pragma unroll
    for (int ih = 0; ih < 2; ih++) {          // ii = 4*ih
        float4 tv[G];
        #pragma unroll
        for (int g = 0; g < G; g++)
            tv[g] = __ldg(reinterpret_cast<const float4*>(
                Tb0 + (size_t)g * (9 * 32 * 8) + ih * 4));

        #pragma unroll
        for (int jj = 0; jj < 4; jj++) {      // i = 4*ih + jj
            ull t2[G];
            #pragma unroll
            for (int g = 0; g < G; g++) {
                const float tj = (jj == 0) ? tv[g].x : (jj == 1) ? tv[g].y
                               : (jj == 2) ? tv[g].z : tv[g].w;
                t2[g] = pk2(tj, tj);
            }
            const int i = 4 * ih + jj;
            #pragma unroll
            for (int c4 = 0; c4 < 4; c4++) {
                const ulonglong2 w2 = *reinterpret_cast<const ulonglong2*>(
                    Wtb + (i * 4 + c4) * 128);
                #pragma unroll
                for (int g = 0; g < G; g++) {
                    pr2[g][2 * c4 + 0] = fma2(w2.x, t2[g], pr2[g][2 * c4 + 0]);
                    pr2[g][2 * c4 + 1] = fma2(w2.y, t2[g], pr2[g][2 * c4 + 1]);
                }
            }
        }
    }

    // One-time unpack to scalar priors (register-pair aliasing; routing below
    // is byte-identical to the proven round-7 code).
    float pr[G][16];
    #pragma unroll
    for (int g = 0; g < G; g++)
        #pragma unroll
        for (int c2 = 0; c2 < 8; c2++)
            upk(pr2[g][c2], pr[g][2 * c2], pr[g][2 * c2 + 1]);

    // ---- Dynamic routing: fully unrolled 3 iterations ----
    float logit[G];
    #pragma unroll
    for (int g = 0; g < G; g++) logit[g] = 0.0f;

    #pragma unroll
    for (int it = 0; it < 3; it++) {
        float e[G];
        if (it > 0) {
            // exp + denominator reduce (4 sums via one compacted 9-SHFL butterfly)
            #pragma unroll
            for (int g = 0; g < G; g++) e[g] = __expf(logit[g]);
            float d0 = e[0], d1 = e[1], d2 = e[2], d3 = e[3];
            d0 += __shfl_xor_sync(0xffffffffu, d0, 16);
            d1 += __shfl_xor_sync(0xffffffffu, d1, 16);
            d2 += __shfl_xor_sync(0xffffffffu, d2, 16);
            d3 += __shfl_xor_sync(0xffffffffu, d3, 16);
            {
                const bool sel = (lane & 8) != 0;
                float m0 = sel ? d2 : d0, o0 = sel ? d0 : d2;
                float m1 = sel ? d3 : d1, o1 = sel ? d1 : d3;
                o0 = __shfl_xor_sync(0xffffffffu, o0, 8);
                o1 = __shfl_xor_sync(0xffffffffu, o1, 8);
                d0 = m0 + o0; d1 = m1 + o1;
            }
            {
                const bool sel = (lane & 4) != 0;
                float m = sel ? d1 : d0, ox = sel ? d0 : d1;
                ox = __shfl_xor_sync(0xffffffffu, ox, 4);
                d0 = m + ox;
            }
            d0 += __shfl_xor_sync(0xffffffffu, d0, 2);
            d0 += __shfl_xor_sync(0xffffffffu, d0, 1);
            // lane l (l<16, l%4==0) holds D for g = 2*bit3(l) + bit2(l)
            if (lane < 16 && (lane & 3) == 0)
                s_wsum[warp][((lane >> 3) << 1) | ((lane >> 2) & 1)] = d0;
        }

        // weighted (or raw, iter 0) route-sum reduction per g
        #pragma unroll
        for (int g = 0; g < G; g++) {
            float red[16];
            if (it == 0) {
                #pragma unroll
                for (int c = 0; c < 16; c++) red[c] = pr[g][c];
            } else {
                #pragma unroll
                for (int c = 0; c < 16; c++) red[c] = e[g] * pr[g][c];
            }
            const float r0 = reduce_warp16(red, lane);
            if (lane < 16) s_wpart[warp][g * 16 + lane] = r0;
        }
        __syncthreads();

        // Parallel finalize: warp g (g<4) handles group g.
        if (warp < G) {
            const int g = warp;
            float val = 0.0f;
            if (lane < 16) {
                #pragma unroll
                for (int w = 0; w < NWARPS; w++)
                    val += s_wpart[w][g * 16 + lane];
            }
            if (it == 0) {
                val *= (1.0f / 288.0f);
            } else {
                float dsum = 0.0f;
                #pragma unroll
                for (int w = 0; w < NWARPS; w++)
                    dsum += s_wsum[w][g];
                val = __fdividef(val, dsum);
            }
            float sq = val * val;
            sq += __shfl_xor_sync(0xffffffffu, sq, 8);
            sq += __shfl_xor_sync(0xffffffffu, sq, 4);
            sq += __shfl_xor_sync(0xffffffffu, sq, 2);
            sq += __shfl_xor_sync(0xffffffffu, sq, 1);
            const float scale = __fdividef(sqrtf(sq), 1.0f + sq);
            const float ov = val * scale;
            if (lane < 16) {
                if (it == 2) {
                    out[(size_t)(b * 512 + o * 16 + lane) * 144
                        + oh * 12 + ow0 + g] = ov;
                } else {
                    s_vout[g * 16 + lane] = ov;
                }
            }
        }

        // logits += priors . v
        if (it < 2) {
            __syncthreads();
            #pragma unroll
            for (int g = 0; g < G; g++) {
                float acc = 0.0f;
                #pragma unroll
                for (int c = 0; c < 16; c++)
                    acc = fmaf(pr[g][c], s_vout[g * 16 + c], acc);
                logit[g] += acc;
            }
        }
    }
}

extern "C" void kernel_launch(void* const* d_in, const int* in_sizes, int n_in,
                              void* d_out, int out_size)
{
    (void)in_sizes; (void)n_in; (void)out_size;
    const float* x = (const float*)d_in[0];
    const float* w = (const float*)d_in[1];
    float* out = (float*)d_out;

    prep_kernel<<<2448, 256>>>(w, x);  // 1152 repack blocks + 1296 tile blocks

    dim3 grid(144, 32);   // 576/G n-groups  x  32 output caps
    caps_kernel<<<grid, NTHREADS>>>(out);
}

// round 11
// speedup vs baseline: 1.1820x; 1.0678x over previous
#include <cuda_runtime.h>

// CapsuleLayer fused kernel, round 10: G=2 + 3 blocks/SM for occupancy.
// x:      (4, 256, 14, 14) fp32          d_in[0]
// weight: (32, 288, 8, 16) fp32          d_in[1]   [o][k][i][c], k = kk*32+inc
// out:    (4, 512, 12, 12) fp32          d_out     channel = o*16 + c

#define G 2
#define NTHREADS 288
#define NWARPS 9

typedef unsigned long long ull;

// Repacked weights: Wt[o][kk][i][c4][lane][4] : 32*9*8*4*32*4 floats
__device__ float g_Wt[32 * 9 * 8 * 4 * 32 * 4];
// Repacked x tiles: T[n][kk][lane=inc][i] : 576*9*32*8 floats = 5.3MB
__device__ float g_tiles[576 * 9 * 32 * 8];

// Merged prep: blocks [0,1152) repack weights, [1152,2448) build x tiles.
__global__ void prep_kernel(const float* __restrict__ W,
                            const float* __restrict__ x)
{
    const int bx = blockIdx.x;
    if (bx < 1152) {
        const int idx = bx * 256 + threadIdx.x;   // 0 .. 294911 float4s
        const int c4 = idx & 3;
        const int i  = (idx >> 2) & 7;
        const int t  = idx >> 5;
        const int k  = t % 288;
        const int o  = t / 288;
        const int kk = k >> 5;
        const int ln = k & 31;
        const int dst4 = (((o * 9 + kk) * 8 + i) * 4 + c4) * 32 + ln;
        reinterpret_cast<float4*>(g_Wt)[dst4] =
            reinterpret_cast<const float4*>(W)[idx];
    } else {
        const int idx = (bx - 1152) * 256 + threadIdx.x;  // 0 .. 331775 float4s
        const int ihalf = idx & 1;
        const int lane  = (idx >> 1) & 31;
        const int t     = idx >> 6;        // n*9 + kk, 0..5183
        const int kk    = t % 9;
        const int n     = t / 9;
        const int b     = n / 144;
        const int rr    = n - b * 144;
        const int oh    = rr / 12;
        const int ow    = rr - oh * 12;
        const int kh    = kk / 3;
        const int kw    = kk - kh * 3;

        const float* src = x + (size_t)b * (256 * 196)
                             + (size_t)(lane * 8 + ihalf * 4) * 196
                             + (oh + kh) * 14 + (ow + kw);
        float4 v;
        v.x = __ldg(src);
        v.y = __ldg(src + 196);
        v.z = __ldg(src + 392);
        v.w = __ldg(src + 588);
        reinterpret_cast<float4*>(g_tiles)[idx] = v;
    }
}

// ---- packed f32x2 helpers ----
__device__ __forceinline__ ull pk2(float a, float b) {
    ull r; asm("mov.b64 %0, {%1, %2};" : "=l"(r) : "f"(a), "f"(b)); return r;
}
__device__ __forceinline__ void upk(ull v, float& a, float& b) {
    asm("mov.b64 {%0, %1}, %2;" : "=f"(a), "=f"(b) : "l"(v));
}
__device__ __forceinline__ ull fma2(ull a, ull b, ull c) {
    ull d; asm("fma.rn.f32x2 %0, %1, %2, %3;" : "=l"(d) : "l"(a), "l"(b), "l"(c));
    return d;
}

// Reduce 16 values across the full warp with log-halving compaction.
// Output: lane l returns total sum for c = (l & 15).
__device__ __forceinline__ float reduce_warp16(float red[16], int lane)
{
    #pragma unroll
    for (int j = 0; j < 16; j++)
        red[j] += __shfl_xor_sync(0xffffffffu, red[j], 16);
    {
        const bool sel = (lane & 8) != 0;
        #pragma unroll
        for (int j = 0; j < 8; j++) {
            float mine  = sel ? red[j + 8] : red[j];
            float other = sel ? red[j]     : red[j + 8];
            other = __shfl_xor_sync(0xffffffffu, other, 8);
            red[j] = mine + other;
        }
    }
    {
        const bool sel = (lane & 4) != 0;
        #pragma unroll
        for (int j = 0; j < 4; j++) {
            float mine  = sel ? red[j + 4] : red[j];
            float other = sel ? red[j]     : red[j + 4];
            other = __shfl_xor_sync(0xffffffffu, other, 4);
            red[j] = mine + other;
        }
    }
    {
        const bool sel = (lane & 2) != 0;
        #pragma unroll
        for (int j = 0; j < 2; j++) {
            float mine  = sel ? red[j + 2] : red[j];
            float other = sel ? red[j]     : red[j + 2];
            other = __shfl_xor_sync(0xffffffffu, other, 2);
            red[j] = mine + other;
        }
    }
    {
        const bool sel = (lane & 1) != 0;
        float mine  = sel ? red[1] : red[0];
        float other = sel ? red[0] : red[1];
        other = __shfl_xor_sync(0xffffffffu, other, 1);
        red[0] = mine + other;
    }
    return red[0];
}

__global__ __launch_bounds__(NTHREADS, 3)
void caps_kernel(float* __restrict__ out)
{
    __shared__ float s_wsum[NWARPS][G];       // per-warp exp-sum partials
    __shared__ float s_wpart[NWARPS][G * 16]; // per-warp output partials
    __shared__ float s_vout[G * 16];          // squashed output vectors [g][c]

    const int tid  = threadIdx.x;
    const int lane = tid & 31;
    const int warp = tid >> 5;

    const int o   = blockIdx.y;
    const int n0  = blockIdx.x * G;
    const int b   = n0 / 144;
    const int rr  = n0 - b * 144;
    const int oh  = rr / 12;
    const int ow0 = rr - oh * 12;

    // float offset = (o*9+warp)*4096 + (i*4+c4)*128 + lane*4
    const float* Wtb = g_Wt + ((size_t)(o * 9 + warp) * 4096) + lane * 4;
    // tile base: ((n*9+warp)*32+lane)*8
    const float* Tb0 = g_tiles + (((size_t)n0 * 9 + warp) * 32 + lane) * 8;

    // ---- Priors GEMM, packed f32x2: pr2[g][c2] = (c=2*c2, c=2*c2+1) ----
    ull pr2[G][8];
    #pragma unroll
    for (int g = 0; g < G; g++)
        #pragma unroll
        for (int c2 = 0; c2 < 8; c2++)
            pr2[g][c2] = 0ull;

    #pragma unroll
    for (int ih = 0; ih < 2; ih++) {          // ii = 4*ih
        float4 tv[G];
        #pragma unroll
        for (int g = 0; g < G; g++)
            tv[g] = __ldg(reinterpret_cast<const float4*>(
                Tb0 + (size_t)g * (9 * 32 * 8) + ih * 4));

        #pragma unroll
        for (int jj = 0; jj < 4; jj++) {      // i = 4*ih + jj
            ull t2[G];
            #pragma unroll
            for (int g = 0; g < G; g++) {
                const float tj = (jj == 0) ? tv[g].x : (jj == 1) ? tv[g].y
                               : (jj == 2) ? tv[g].z : tv[g].w;
                t2[g] = pk2(tj, tj);
            }
            const int i = 4 * ih + jj;
            #pragma unroll
            for (int c4 = 0; c4 < 4; c4++) {
                const ulonglong2 w2 = *reinterpret_cast<const ulonglong2*>(
                    Wtb + (i * 4 + c4) * 128);
                #pragma unroll
                for (int g = 0; g < G; g++) {
                    pr2[g][2 * c4 + 0] = fma2(w2.x, t2[g], pr2[g][2 * c4 + 0]);
                    pr2[g][2 * c4 + 1] = fma2(w2.y, t2[g], pr2[g][2 * c4 + 1]);
                }
            }
        }
    }

    // One-time unpack to scalar priors (register-pair aliasing).
    float pr[G][16];
    #pragma unroll
    for (int g = 0; g < G; g++)
        #pragma unroll
        for (int c2 = 0; c2 < 8; c2++)
            upk(pr2[g][c2], pr[g][2 * c2], pr[g][2 * c2 + 1]);

    // ---- Dynamic routing: fully unrolled 3 iterations ----
    float logit[G];
    #pragma unroll
    for (int g = 0; g < G; g++) logit[g] = 0.0f;

    #pragma unroll
    for (int it = 0; it < 3; it++) {
        float e[G];
        if (it > 0) {
            // exp + denominator reduce (2 sums via one compacted 6-SHFL butterfly)
            #pragma unroll
            for (int g = 0; g < G; g++) e[g] = __expf(logit[g]);
            float d0 = e[0], d1 = e[1];
            d0 += __shfl_xor_sync(0xffffffffu, d0, 16);
            d1 += __shfl_xor_sync(0xffffffffu, d1, 16);
            {
                const bool sel = (lane & 8) != 0;
                float m = sel ? d1 : d0, ox = sel ? d0 : d1;
                ox = __shfl_xor_sync(0xffffffffu, ox, 8);
                d0 = m + ox;
            }
            d0 += __shfl_xor_sync(0xffffffffu, d0, 4);
            d0 += __shfl_xor_sync(0xffffffffu, d0, 2);
            d0 += __shfl_xor_sync(0xffffffffu, d0, 1);
            // lane l (l<16, l%8==0) holds D for g = bit3(l)
            if (lane < 16 && (lane & 7) == 0)
                s_wsum[warp][lane >> 3] = d0;
        }

        // weighted (or raw, iter 0) route-sum reduction per g
        #pragma unroll
        for (int g = 0; g < G; g++) {
            float red[16];
            if (it == 0) {
                #pragma unroll
                for (int c = 0; c < 16; c++) red[c] = pr[g][c];
            } else {
                #pragma unroll
                for (int c = 0; c < 16; c++) red[c] = e[g] * pr[g][c];
            }
            const float r0 = reduce_warp16(red, lane);
            if (lane < 16) s_wpart[warp][g * 16 + lane] = r0;
        }
        __syncthreads();

        // Parallel finalize: warp g (g<G) handles group g.
        if (warp < G) {
            const int g = warp;
            float val = 0.0f;
            if (lane < 16) {
                #pragma unroll
                for (int w = 0; w < NWARPS; w++)
                    val += s_wpart[w][g * 16 + lane];
            }
            if (it == 0) {
                val *= (1.0f / 288.0f);
            } else {
                float dsum = 0.0f;
                #pragma unroll
                for (int w = 0; w < NWARPS; w++)
                    dsum += s_wsum[w][g];
                val = __fdividef(val, dsum);
            }
            float sq = val * val;
            sq += __shfl_xor_sync(0xffffffffu, sq, 8);
            sq += __shfl_xor_sync(0xffffffffu, sq, 4);
            sq += __shfl_xor_sync(0xffffffffu, sq, 2);
            sq += __shfl_xor_sync(0xffffffffu, sq, 1);
            const float scale = __fdividef(sqrtf(sq), 1.0f + sq);
            const float ov = val * scale;
            if (lane < 16) {
                if (it == 2) {
                    out[(size_t)(b * 512 + o * 16 + lane) * 144
                        + oh * 12 + ow0 + g] = ov;
                } else {
                    s_vout[g * 16 + lane] = ov;
                }
            }
        }

        // logits += priors . v
        if (it < 2) {
            __syncthreads();
            #pragma unroll
            for (int g = 0; g < G; g++) {
                float acc = 0.0f;
                #pragma unroll
                for (int c = 0; c < 16; c++)
                    acc = fmaf(pr[g][c], s_vout[g * 16 + c], acc);
                logit[g] += acc;
            }
        }
    }
}

extern "C" void kernel_launch(void* const* d_in, const int* in_sizes, int n_in,
                              void* d_out, int out_size)
{
    (void)in_sizes; (void)n_in; (void)out_size;
    const float* x = (const float*)d_in[0];
    const float* w = (const float*)d_in[1];
    float* out = (float*)d_out;

    prep_kernel<<<2448, 256>>>(w, x);  // 1152 repack blocks + 1296 tile blocks

    dim3 grid(576 / G, 32);   // 288 x 32, each block does G n-positions
    caps_kernel<<<grid, NTHREADS>>>(out);
}

// round 14
// speedup vs baseline: 1.3533x; 1.1449x over previous
#include <cuda_runtime.h>

// CapsuleLayer fused kernel, round 13: round-11 winner (G=2, occ 3) with the
// two per-g 31-SHFL butterflies merged into ONE 31-SHFL 32-value butterfly
// (lane l ends holding the route-sum for g=l>>4, c=l&15).
// x:      (4, 256, 14, 14) fp32          d_in[0]
// weight: (32, 288, 8, 16) fp32          d_in[1]   [o][k][i][c], k = kk*32+inc
// out:    (4, 512, 12, 12) fp32          d_out     channel = o*16 + c

#define G 2
#define NTHREADS 288
#define NWARPS 9

typedef unsigned long long ull;

// Repacked weights: Wt[o][kk][i][c4][lane][4] : 32*9*8*4*32*4 floats
__device__ float g_Wt[32 * 9 * 8 * 4 * 32 * 4];
// Repacked x tiles: T[n][kk][lane=inc][i] : 576*9*32*8 floats = 5.3MB
__device__ float g_tiles[576 * 9 * 32 * 8];

// Merged prep: blocks [0,1152) repack weights, [1152,2448) build x tiles.
__global__ void prep_kernel(const float* __restrict__ W,
                            const float* __restrict__ x)
{
    const int bx = blockIdx.x;
    if (bx < 1152) {
        const int idx = bx * 256 + threadIdx.x;   // 0 .. 294911 float4s
        const int c4 = idx & 3;
        const int i  = (idx >> 2) & 7;
        const int t  = idx >> 5;
        const int k  = t % 288;
        const int o  = t / 288;
        const int kk = k >> 5;
        const int ln = k & 31;
        const int dst4 = (((o * 9 + kk) * 8 + i) * 4 + c4) * 32 + ln;
        reinterpret_cast<float4*>(g_Wt)[dst4] =
            reinterpret_cast<const float4*>(W)[idx];
    } else {
        const int idx = (bx - 1152) * 256 + threadIdx.x;  // 0 .. 331775 float4s
        const int ihalf = idx & 1;
        const int lane  = (idx >> 1) & 31;
        const int t     = idx >> 6;        // n*9 + kk, 0..5183
        const int kk    = t % 9;
        const int n     = t / 9;
        const int b     = n / 144;
        const int rr    = n - b * 144;
        const int oh    = rr / 12;
        const int ow    = rr - oh * 12;
        const int kh    = kk / 3;
        const int kw    = kk - kh * 3;

        const float* src = x + (size_t)b * (256 * 196)
                             + (size_t)(lane * 8 + ihalf * 4) * 196
                             + (oh + kh) * 14 + (ow + kw);
        float4 v;
        v.x = __ldg(src);
        v.y = __ldg(src + 196);
        v.z = __ldg(src + 392);
        v.w = __ldg(src + 588);
        reinterpret_cast<float4*>(g_tiles)[idx] = v;
    }
}

// ---- packed f32x2 helpers ----
__device__ __forceinline__ ull pk2(float a, float b) {
    ull r; asm("mov.b64 %0, {%1, %2};" : "=l"(r) : "f"(a), "f"(b)); return r;
}
__device__ __forceinline__ void upk(ull v, float& a, float& b) {
    asm("mov.b64 {%0, %1}, %2;" : "=f"(a), "=f"(b) : "l"(v));
}
__device__ __forceinline__ ull fma2(ull a, ull b, ull c) {
    ull d; asm("fma.rn.f32x2 %0, %1, %2, %3;" : "=l"(d) : "l"(a), "l"(b), "l"(c));
    return d;
}

__global__ __launch_bounds__(NTHREADS, 3)
void caps_kernel(float* __restrict__ out)
{
    __shared__ float s_wsum[NWARPS][G];        // per-warp exp-sum partials
    __shared__ float s_wpart[NWARPS][G * 16];  // per-warp output partials [j=g*16+c]
    __shared__ float s_vout[G * 16];           // squashed output vectors [g][c]

    const int tid  = threadIdx.x;
    const int lane = tid & 31;
    const int warp = tid >> 5;

    const int o   = blockIdx.y;
    const int n0  = blockIdx.x * G;
    const int b   = n0 / 144;
    const int rr  = n0 - b * 144;
    const int oh  = rr / 12;
    const int ow0 = rr - oh * 12;

    // float offset = (o*9+warp)*4096 + (i*4+c4)*128 + lane*4
    const float* Wtb = g_Wt + ((size_t)(o * 9 + warp) * 4096) + lane * 4;
    // tile base: ((n*9+warp)*32+lane)*8
    const float* Tb0 = g_tiles + (((size_t)n0 * 9 + warp) * 32 + lane) * 8;

    // ---- Priors GEMM, packed f32x2: pr2[g][c2] = (c=2*c2, c=2*c2+1) ----
    ull pr2[G][8];
    #pragma unroll
    for (int g = 0; g < G; g++)
        #pragma unroll
        for (int c2 = 0; c2 < 8; c2++)
            pr2[g][c2] = 0ull;

    #pragma unroll
    for (int ih = 0; ih < 2; ih++) {          // ii = 4*ih
        float4 tv[G];
        #pragma unroll
        for (int g = 0; g < G; g++)
            tv[g] = __ldg(reinterpret_cast<const float4*>(
                Tb0 + (size_t)g * (9 * 32 * 8) + ih * 4));

        #pragma unroll
        for (int jj = 0; jj < 4; jj++) {      // i = 4*ih + jj
            ull t2[G];
            #pragma unroll
            for (int g = 0; g < G; g++) {
                const float tj = (jj == 0) ? tv[g].x : (jj == 1) ? tv[g].y
                               : (jj == 2) ? tv[g].z : tv[g].w;
                t2[g] = pk2(tj, tj);
            }
            const int i = 4 * ih + jj;
            #pragma unroll
            for (int c4 = 0; c4 < 4; c4++) {
                const ulonglong2 w2 = *reinterpret_cast<const ulonglong2*>(
                    Wtb + (i * 4 + c4) * 128);
                #pragma unroll
                for (int g = 0; g < G; g++) {
                    pr2[g][2 * c4 + 0] = fma2(w2.x, t2[g], pr2[g][2 * c4 + 0]);
                    pr2[g][2 * c4 + 1] = fma2(w2.y, t2[g], pr2[g][2 * c4 + 1]);
                }
            }
        }
    }

    // One-time unpack to scalar priors (register-pair aliasing).
    float pr[G][16];
    #pragma unroll
    for (int g = 0; g < G; g++)
        #pragma unroll
        for (int c2 = 0; c2 < 8; c2++)
            upk(pr2[g][c2], pr[g][2 * c2], pr[g][2 * c2 + 1]);

    // ---- Dynamic routing: fully unrolled 3 iterations ----
    float logit[G];
    #pragma unroll
    for (int g = 0; g < G; g++) logit[g] = 0.0f;

    #pragma unroll
    for (int it = 0; it < 3; it++) {
        float e[G];
        if (it > 0) {
            // exp + denominator reduce (2 sums via one compacted 6-SHFL butterfly)
            #pragma unroll
            for (int g = 0; g < G; g++) e[g] = __expf(logit[g]);
            float d0 = e[0], d1 = e[1];
            {
                const bool sel = (lane & 16) != 0;
                float m = sel ? d1 : d0, ox = sel ? d0 : d1;
                ox = __shfl_xor_sync(0xffffffffu, ox, 16);
                d0 = m + ox;
            }
            d0 += __shfl_xor_sync(0xffffffffu, d0, 8);
            d0 += __shfl_xor_sync(0xffffffffu, d0, 4);
            d0 += __shfl_xor_sync(0xffffffffu, d0, 2);
            d0 += __shfl_xor_sync(0xffffffffu, d0, 1);
            // lane l holds D for g = bit4(l); lanes 0 and 16 write
            if ((lane & 15) == 0)
                s_wsum[warp][lane >> 4] = d0;
        }

        // Merged 32-value (2g x 16c) route-sum butterfly: 31 SHFL total.
        // After all stages, lane l holds the warp sum for j = l (g=l>>4, c=l&15).
        float red[16];
        {
            const bool sel = (lane & 16) != 0;
            #pragma unroll
            for (int j = 0; j < 16; j++) {
                float a = pr[0][j];
                float b2 = pr[1][j];
                if (it > 0) { a *= e[0]; b2 *= e[1]; }
                float mine  = sel ? b2 : a;
                float other = sel ? a  : b2;
                other = __shfl_xor_sync(0xffffffffu, other, 16);
                red[j] = mine + other;
            }
        }
        {
            const bool sel = (lane & 8) != 0;
            #pragma unroll
            for (int j = 0; j < 8; j++) {
                float mine  = sel ? red[j + 8] : red[j];
                float other = sel ? red[j]     : red[j + 8];
                other = __shfl_xor_sync(0xffffffffu, other, 8);
                red[j] = mine + other;
            }
        }
        {
            const bool sel = (lane & 4) != 0;
            #pragma unroll
            for (int j = 0; j < 4; j++) {
                float mine  = sel ? red[j + 4] : red[j];
                float other = sel ? red[j]     : red[j + 4];
                other = __shfl_xor_sync(0xffffffffu, other, 4);
                red[j] = mine + other;
            }
        }
        {
            const bool sel = (lane & 2) != 0;
            #pragma unroll
            for (int j = 0; j < 2; j++) {
                float mine  = sel ? red[j + 2] : red[j];
                float other = sel ? red[j]     : red[j + 2];
                other = __shfl_xor_sync(0xffffffffu, other, 2);
                red[j] = mine + other;
            }
        }
        {
            const bool sel = (lane & 1) != 0;
            float mine  = sel ? red[1] : red[0];
            float other = sel ? red[0] : red[1];
            other = __shfl_xor_sync(0xffffffffu, other, 1);
            red[0] = mine + other;
        }
        s_wpart[warp][lane] = red[0];
        __syncthreads();

        // Parallel finalize: warp g (g<G) handles group g.
        if (warp < G) {
            const int g = warp;
            float val = 0.0f;
            if (lane < 16) {
                #pragma unroll
                for (int w = 0; w < NWARPS; w++)
                    val += s_wpart[w][g * 16 + lane];
            }
            if (it == 0) {
                val *= (1.0f / 288.0f);
            } else {
                float dsum = 0.0f;
                #pragma unroll
                for (int w = 0; w < NWARPS; w++)
                    dsum += s_wsum[w][g];
                val = __fdividef(val, dsum);
            }
            float sq = val * val;
            sq += __shfl_xor_sync(0xffffffffu, sq, 8);
            sq += __shfl_xor_sync(0xffffffffu, sq, 4);
            sq += __shfl_xor_sync(0xffffffffu, sq, 2);
            sq += __shfl_xor_sync(0xffffffffu, sq, 1);
            const float scale = __fdividef(sqrtf(sq), 1.0f + sq);
            const float ov = val * scale;
            if (lane < 16) {
                if (it == 2) {
                    out[(size_t)(b * 512 + o * 16 + lane) * 144
                        + oh * 12 + ow0 + g] = ov;
                } else {
                    s_vout[g * 16 + lane] = ov;
                }
            }
        }

        // logits += priors . v
        if (it < 2) {
            __syncthreads();
            #pragma unroll
            for (int g = 0; g < G; g++) {
                float acc = 0.0f;
                #pragma unroll
                for (int c = 0; c < 16; c++)
                    acc = fmaf(pr[g][c], s_vout[g * 16 + c], acc);
                logit[g] += acc;
            }
        }
    }
}

extern "C" void kernel_launch(void* const* d_in, const int* in_sizes, int n_in,
                              void* d_out, int out_size)
{
    (void)in_sizes; (void)n_in; (void)out_size;
    const float* x = (const float*)d_in[0];
    const float* w = (const float*)d_in[1];
    float* out = (float*)d_out;

    prep_kernel<<<2448, 256>>>(w, x);  // 1152 repack blocks + 1296 tile blocks

    dim3 grid(576 / G, 32);   // 288 x 32, each block does G n-positions
    caps_kernel<<<grid, NTHREADS>>>(out);
}